// round 11
// baseline (speedup 1.0000x reference)
#include <cuda_runtime.h>
#include <cuda_fp16.h>
#include <cstdint>

#define BATCH   2048
#define FDIM    512
#define NTREES  512
#define NCOLS   2560
#define TDEPTH  5
#define NLEAF   32

#define BM      64       // batch rows per CTA
#define TB      32
#define BN      160
#define KC      64       // 64 fp16 = 128B rows
#define NCHUNK  8
#define NTHR    256      // 8 warps: 2(M) x 4(N), warp tile 32x40
#define NSTAGE  2

__device__ __half g_Xh[BATCH * FDIM];
__device__ __half g_Wh[NCOLS * FDIM];

// smem per CTA: 2 stages x (A 64x128B=8KB + B 160x128B=20KB) = 57344;
// s_D [64][162] f32 = 41472 reuses stage area; thr/it tables above.
#define STAGE_BYTES 28672
#define OFF_THR     57344
#define OFF_IT      (OFF_THR + 640)
#define SMEM_BYTES  (OFF_IT + 640)

__device__ __forceinline__ uint32_t smem_u32(const void* p) {
    uint32_t a;
    asm("{ .reg .u64 t; cvta.to.shared.u64 t, %1; cvt.u32.u64 %0, t; }"
        : "=r"(a) : "l"(p));
    return a;
}
__device__ __forceinline__ void cpa16(uint32_t dst, const void* src) {
    asm volatile("cp.async.cg.shared.global [%0], [%1], 16;"
                 :: "r"(dst), "l"(src));
}
#define CP_COMMIT() asm volatile("cp.async.commit_group;" ::: "memory")

__device__ __forceinline__ void mma16(float* d, uint2 aP, uint2 aQ, uint2 b) {
    asm volatile(
        "mma.sync.aligned.m16n8k16.row.col.f32.f16.f16.f32 "
        "{%0,%1,%2,%3}, {%4,%5,%6,%7}, {%8,%9}, {%0,%1,%2,%3};"
        : "+f"(d[0]), "+f"(d[1]), "+f"(d[2]), "+f"(d[3])
        : "r"(aP.x), "r"(aQ.x), "r"(aP.y), "r"(aQ.y), "r"(b.x), "r"(b.y));
}

__device__ __forceinline__ float fma_sat(float a, float b, float c) {
    float r;
    asm("fma.rn.sat.f32 %0, %1, %2, %3;" : "=f"(r) : "f"(a), "f"(b), "f"(c));
    return r;
}

__device__ __forceinline__ void pack16(__half* dst, const float* h) {
    uint32_t w[8];
    #pragma unroll
    for (int j = 0; j < 4; j++) {
        __half2 lo = __floats2half2_rn(h[2 * j],     h[2 * j + 1]);
        __half2 hi = __floats2half2_rn(h[2 * j + 8], h[2 * j + 9]);
        w[2 * j]     = *(uint32_t*)&lo;
        w[2 * j + 1] = *(uint32_t*)&hi;
    }
    *(uint4*)dst       = make_uint4(w[0], w[1], w[2], w[3]);
    *(uint4*)(dst + 8) = make_uint4(w[4], w[5], w[6], w[7]);
}

// ---------------------------------------------------------------------------
// Fused prep: blocks [0,80) = softmax+permute W ; blocks [80,208) = permute X
// ---------------------------------------------------------------------------
__global__ void prep_kernel(const float* __restrict__ fa,
                            const float* __restrict__ x) {
    extern __shared__ float st[];
    const int tid = threadIdx.x;

    if (blockIdx.x >= 80) {
        const int base = (blockIdx.x - 80) * 512 + tid;
        float h[2][16];
        int fbo[2];
        #pragma unroll
        for (int u = 0; u < 2; u++) {
            const int id  = base + u * 256;
            const int row = id >> 5;
            const int c   = (id >> 2) & 7;
            const int s   = id & 3;
            const float* src = x + (size_t)row * FDIM + c * 64 + s * 16;
            #pragma unroll
            for (int q = 0; q < 4; q++) {
                float4 v = *(const float4*)(src + q * 4);
                h[u][q * 4 + 0] = v.x; h[u][q * 4 + 1] = v.y;
                h[u][q * 4 + 2] = v.z; h[u][q * 4 + 3] = v.w;
            }
            const int fb = (s * 4 + 4 * (row & 3)) & 15;
            fbo[u] = row * FDIM + c * 64 + fb * 4;
        }
        #pragma unroll
        for (int u = 0; u < 2; u++)
            pack16(g_Xh + (size_t)fbo[u], h[u]);
        return;
    }

    __shared__ float red[8][32];
    __shared__ float s_mx[32], s_inv[32];
    const int lx = tid & 31;
    const int ry = tid >> 5;
    const int c0 = blockIdx.x * 32;

    #pragma unroll
    for (int r = 0; r < 16; r++) {
        int q = tid + r * 256;
        int f = q >> 3, cq = q & 7;
        float4 v = *(const float4*)&fa[(size_t)f * NCOLS + c0 + cq * 4];
        float* p = &st[f * 33 + cq * 4];
        p[0] = v.x; p[1] = v.y; p[2] = v.z; p[3] = v.w;
    }
    __syncthreads();

    float m = -1e30f;
    for (int f = ry; f < FDIM; f += 8) m = fmaxf(m, st[f * 33 + lx]);
    red[ry][lx] = m;
    __syncthreads();
    if (ry == 0) {
        float mm = red[0][lx];
        #pragma unroll
        for (int r = 1; r < 8; r++) mm = fmaxf(mm, red[r][lx]);
        s_mx[lx] = mm;
    }
    __syncthreads();
    const float mx = s_mx[lx];

    float s = 0.f;
    for (int f = ry; f < FDIM; f += 8) {
        float e = __expf(st[f * 33 + lx] - mx);
        st[f * 33 + lx] = e;
        s += e;
    }
    red[ry][lx] = s;
    __syncthreads();
    if (ry == 0) {
        float t = 0.f;
        #pragma unroll
        for (int r = 0; r < 8; r++) t += red[r][lx];
        s_inv[lx] = 1.0f / t;
    }
    __syncthreads();

    const int c       = tid >> 5;
    const int n_local = tid & 31;
    const int n       = c0 + n_local;
    const float inv   = s_inv[n_local];
    const int rot4    = 4 * (n_local & 3);

    #pragma unroll
    for (int sstep = 0; sstep < 4; sstep++) {
        const int kb = c * 64 + sstep * 16;
        float h[16];
        #pragma unroll
        for (int p = 0; p < 16; p++)
            h[p] = st[(kb + p) * 33 + n_local] * inv;
        const int fb = (sstep * 4 + rot4) & 15;
        pack16(g_Wh + (size_t)n * FDIM + c * 64 + fb * 4, h);
    }
}

// ---------------------------------------------------------------------------
// Main: fp16 m16n8k16 GEMM 64x160x512 per CTA, 8 warps (2x4), warp 32x40,
// 2-stage cp.async, 3 CTAs/SM (24 warps), fused tree epilogue.
// ---------------------------------------------------------------------------
__global__ __launch_bounds__(NTHR, 3)
void detree_mma_kernel(const float* __restrict__ thr,
                       const float* __restrict__ logt,
                       const float* __restrict__ resp,
                       float* __restrict__ out) {
    extern __shared__ char sm[];
    float* s_thr = (float*)(sm + OFF_THR);
    float* s_it  = (float*)(sm + OFF_IT);
    float* s_D   = (float*)sm;                 // [64][162], reuses stage area
    const uint32_t smb = smem_u32(sm);

    const int tid  = threadIdx.x;
    const int lane = tid & 31;
    const int wid  = tid >> 5;
    const int g    = lane >> 2;
    const int tig  = lane & 3;
    const int wm   = wid >> 2;        // 0..1 -> rows wm*32
    const int wn   = wid & 3;         // 0..3 -> cols wn*40
    const int m0    = blockIdx.y * BM;
    const int tree0 = blockIdx.x * TB;
    const int n0    = tree0 * TDEPTH;

    if (tid < TB * TDEPTH) {
        s_thr[tid] = thr[n0 + tid];
        s_it[tid]  = __expf(-logt[n0 + tid]);
    }

    int fb8[4];
    #pragma unroll
    for (int s = 0; s < 4; s++)
        fb8[s] = (((s * 4 + tig) + 4 * (g & 3)) & 15) * 8;
    const int aRow0 = (wm * 32 + g) * 128;             // + mt*2048 (+1024 hi)
    const int bRow0 = 8192 + (wn * 40 + g) * 128;      // + nt*1024

    const __half* aSrcBase = g_Xh + (size_t)m0 * FDIM;
    const __half* bSrcBase = g_Wh + (size_t)n0 * FDIM;

    auto issue_chunk = [&](int i) {
        const uint32_t aB = smb + (i & 1) * STAGE_BYTES;
        const uint32_t bB = aB + 8192;
        const __half* aS = aSrcBase + i * KC;
        const __half* bS = bSrcBase + i * KC;
        #pragma unroll
        for (int r = 0; r < 2; r++) {          // A: 512 quads
            int id = tid + r * NTHR;
            int row = id >> 3, q = id & 7;
            cpa16(aB + row * 128 + q * 16, aS + (size_t)row * FDIM + q * 8);
        }
        #pragma unroll
        for (int r = 0; r < 5; r++) {          // B: 1280 quads
            int id = tid + r * NTHR;
            int row = id >> 3, q = id & 7;
            cpa16(bB + row * 128 + q * 16, bS + (size_t)row * FDIM + q * 8);
        }
        CP_COMMIT();
    };

    float d[2][5][4];
    #pragma unroll
    for (int mt = 0; mt < 2; mt++)
        #pragma unroll
        for (int nt = 0; nt < 5; nt++)
            #pragma unroll
            for (int q = 0; q < 4; q++) d[mt][nt][q] = 0.f;

    issue_chunk(0);

    for (int i = 0; i < NCHUNK; i++) {
        if (i + 1 < NCHUNK) {                  // stage (i+1)&1 freed by the
            issue_chunk(i + 1);                // end-of-iter barrier of i-1
            asm volatile("cp.async.wait_group 1;" ::: "memory");
        } else {
            asm volatile("cp.async.wait_group 0;" ::: "memory");
        }
        __syncthreads();                       // chunk i visible to all warps

        const char* stB = sm + (i & 1) * STAGE_BYTES;
        #pragma unroll
        for (int s = 0; s < 4; s++) {
            const char* aB = stB + aRow0 + fb8[s];
            const char* bB = stB + bRow0 + fb8[s];
            uint2 aP[2], aQ[2], bf[5];
            #pragma unroll
            for (int mt = 0; mt < 2; mt++) {
                aP[mt] = *(const uint2*)(aB + mt * 2048);
                aQ[mt] = *(const uint2*)(aB + mt * 2048 + 1024);
            }
            #pragma unroll
            for (int nt = 0; nt < 5; nt++)
                bf[nt] = *(const uint2*)(bB + nt * 1024);
            #pragma unroll
            for (int mt = 0; mt < 2; mt++)
                #pragma unroll
                for (int nt = 0; nt < 5; nt++)
                    mma16(d[mt][nt], aP[mt], aQ[mt], bf[nt]);
        }
        __syncthreads();                       // stage i&1 free for chunk i+2
    }

    // ---- D -> s_D [64][162] (accumulators die here) ----
    #pragma unroll
    for (int mt = 0; mt < 2; mt++) {
        const int row0 = wm * 32 + mt * 16 + g;
        #pragma unroll
        for (int nt = 0; nt < 5; nt++) {
            const int col = wn * 40 + nt * 8 + 2 * tig;
            *(float2*)&s_D[row0 * 162 + col] =
                make_float2(d[mt][nt][0], d[mt][nt][1]);
            *(float2*)&s_D[(row0 + 8) * 162 + col] =
                make_float2(d[mt][nt][2], d[mt][nt][3]);
        }
    }

    // per-thread tree tables (fixed tree per thread)
    const int tr = tid & 31;
    const int rb = tid >> 5;                   // 0..7
    float ga[5], gb[5];
    #pragma unroll
    for (int dd = 0; dd < TDEPTH; dd++) {
        float it = s_it[tr * 5 + dd];
        ga[dd] = 0.5f * it;
        gb[dd] = 0.5f - s_thr[tr * 5 + dd] * ga[dd];
    }
    float r[16], dr[16];
    #pragma unroll
    for (int q = 0; q < 4; q++) {
        float4 vl = *(const float4*)&resp[(size_t)(tree0 + tr) * NLEAF + q * 4];
        float4 vh = *(const float4*)&resp[(size_t)(tree0 + tr) * NLEAF + 16 + q * 4];
        r[4 * q + 0] = vl.x; r[4 * q + 1] = vl.y;
        r[4 * q + 2] = vl.z; r[4 * q + 3] = vl.w;
        dr[4 * q + 0] = vh.x - vl.x; dr[4 * q + 1] = vh.y - vl.y;
        dr[4 * q + 2] = vh.z - vl.z; dr[4 * q + 3] = vh.w - vl.w;
    }
    __syncthreads();

    // ---- epilogue: 8 rows per thread, one tree ----
    #pragma unroll
    for (int t = 0; t < 8; t++) {
        const int row = rb + t * 8;
        const float* fv = &s_D[row * 162 + tr * 5];
        float c1a[5];
        #pragma unroll
        for (int dd = 0; dd < TDEPTH; dd++)
            c1a[dd] = fma_sat(fv[dd], ga[dd], gb[dd]);

        float s4[16];
        #pragma unroll
        for (int i2 = 0; i2 < 16; i2++)
            s4[i2] = fmaf(c1a[4], dr[i2], r[i2]);
        float s3[8];
        #pragma unroll
        for (int i2 = 0; i2 < 8; i2++)
            s3[i2] = fmaf(c1a[3], s4[i2 + 8] - s4[i2], s4[i2]);
        float s2[4];
        #pragma unroll
        for (int i2 = 0; i2 < 4; i2++)
            s2[i2] = fmaf(c1a[2], s3[i2 + 4] - s3[i2], s3[i2]);
        float s1[2];
        #pragma unroll
        for (int i2 = 0; i2 < 2; i2++)
            s1[i2] = fmaf(c1a[1], s2[i2 + 2] - s2[i2], s2[i2]);
        float ssum = fmaf(c1a[0], s1[1] - s1[0], s1[0]);

        out[(size_t)(m0 + row) * NTREES + tree0 + tr] = ssum;
    }
}

extern "C" void kernel_launch(void* const* d_in, const int* in_sizes, int n_in,
                              void* d_out, int out_size) {
    const float* x    = (const float*)d_in[0];
    const float* fa   = (const float*)d_in[1];
    const float* thr  = (const float*)d_in[2];
    const float* logt = (const float*)d_in[3];
    const float* resp = (const float*)d_in[4];
    float* out = (float*)d_out;

    const int sm_prep = 512 * 33 * 4;
    cudaFuncSetAttribute(prep_kernel,
                         cudaFuncAttributeMaxDynamicSharedMemorySize, sm_prep);
    cudaFuncSetAttribute(detree_mma_kernel,
                         cudaFuncAttributeMaxDynamicSharedMemorySize, SMEM_BYTES);

    prep_kernel<<<80 + 128, 256, sm_prep>>>(fa, x);
    detree_mma_kernel<<<dim3(NTREES / TB, BATCH / BM), NTHR, SMEM_BYTES>>>(
        thr, logt, resp, out);
}

// round 12
// speedup vs baseline: 1.1232x; 1.1232x over previous
#include <cuda_runtime.h>
#include <cuda_fp16.h>
#include <cstdint>

#define BATCH   2048
#define FDIM    512
#define NTREES  512
#define NCOLS   2560
#define TDEPTH  5
#define NLEAF   32

#define BM      128      // batch rows per CTA
#define TB      32
#define BN      160
#define KC      64       // 64 fp16 = 128B rows
#define NCHUNK  8
#define NTHR    256      // 8 warps: 2(M) x 4(N), warp tile 64x40
#define NSTAGE  2

__device__ __half g_Xh[BATCH * FDIM];
__device__ __half g_Wh[NCOLS * FDIM];

// smem per CTA: 2 stages x (A 128x128B=16KB + B 160x128B=20KB) = 73728;
// s_D [64][162] f32 = 41472 reuses stage area; thr/it tables above.
#define STAGE_BYTES 36864
#define OFF_THR     73728
#define OFF_IT      (OFF_THR + 640)
#define SMEM_BYTES  (OFF_IT + 640)

__device__ __forceinline__ uint32_t smem_u32(const void* p) {
    uint32_t a;
    asm("{ .reg .u64 t; cvta.to.shared.u64 t, %1; cvt.u32.u64 %0, t; }"
        : "=r"(a) : "l"(p));
    return a;
}
__device__ __forceinline__ void cpa16(uint32_t dst, const void* src) {
    asm volatile("cp.async.cg.shared.global [%0], [%1], 16;"
                 :: "r"(dst), "l"(src));
}
#define CP_COMMIT() asm volatile("cp.async.commit_group;" ::: "memory")

__device__ __forceinline__ void mma16(float* d, uint2 aP, uint2 aQ, uint2 b) {
    asm volatile(
        "mma.sync.aligned.m16n8k16.row.col.f32.f16.f16.f32 "
        "{%0,%1,%2,%3}, {%4,%5,%6,%7}, {%8,%9}, {%0,%1,%2,%3};"
        : "+f"(d[0]), "+f"(d[1]), "+f"(d[2]), "+f"(d[3])
        : "r"(aP.x), "r"(aQ.x), "r"(aP.y), "r"(aQ.y), "r"(b.x), "r"(b.y));
}

__device__ __forceinline__ float fma_sat(float a, float b, float c) {
    float r;
    asm("fma.rn.sat.f32 %0, %1, %2, %3;" : "=f"(r) : "f"(a), "f"(b), "f"(c));
    return r;
}

__device__ __forceinline__ void pack16(__half* dst, const float* h) {
    uint32_t w[8];
    #pragma unroll
    for (int j = 0; j < 4; j++) {
        __half2 lo = __floats2half2_rn(h[2 * j],     h[2 * j + 1]);
        __half2 hi = __floats2half2_rn(h[2 * j + 8], h[2 * j + 9]);
        w[2 * j]     = *(uint32_t*)&lo;
        w[2 * j + 1] = *(uint32_t*)&hi;
    }
    *(uint4*)dst       = make_uint4(w[0], w[1], w[2], w[3]);
    *(uint4*)(dst + 8) = make_uint4(w[4], w[5], w[6], w[7]);
}

// ---------------------------------------------------------------------------
// Fused prep: blocks [0,80) = softmax+permute W ; blocks [80,208) = permute X
// ---------------------------------------------------------------------------
__global__ void prep_kernel(const float* __restrict__ fa,
                            const float* __restrict__ x) {
    extern __shared__ float st[];
    const int tid = threadIdx.x;

    if (blockIdx.x >= 80) {
        const int base = (blockIdx.x - 80) * 512 + tid;
        float h[2][16];
        int fbo[2];
        #pragma unroll
        for (int u = 0; u < 2; u++) {
            const int id  = base + u * 256;
            const int row = id >> 5;
            const int c   = (id >> 2) & 7;
            const int s   = id & 3;
            const float* src = x + (size_t)row * FDIM + c * 64 + s * 16;
            #pragma unroll
            for (int q = 0; q < 4; q++) {
                float4 v = *(const float4*)(src + q * 4);
                h[u][q * 4 + 0] = v.x; h[u][q * 4 + 1] = v.y;
                h[u][q * 4 + 2] = v.z; h[u][q * 4 + 3] = v.w;
            }
            const int fb = (s * 4 + 4 * (row & 3)) & 15;
            fbo[u] = row * FDIM + c * 64 + fb * 4;
        }
        #pragma unroll
        for (int u = 0; u < 2; u++)
            pack16(g_Xh + (size_t)fbo[u], h[u]);
        return;
    }

    __shared__ float red[8][32];
    __shared__ float s_mx[32], s_inv[32];
    const int lx = tid & 31;
    const int ry = tid >> 5;
    const int c0 = blockIdx.x * 32;

    #pragma unroll
    for (int r = 0; r < 16; r++) {
        int q = tid + r * 256;
        int f = q >> 3, cq = q & 7;
        float4 v = *(const float4*)&fa[(size_t)f * NCOLS + c0 + cq * 4];
        float* p = &st[f * 33 + cq * 4];
        p[0] = v.x; p[1] = v.y; p[2] = v.z; p[3] = v.w;
    }
    __syncthreads();

    float m = -1e30f;
    for (int f = ry; f < FDIM; f += 8) m = fmaxf(m, st[f * 33 + lx]);
    red[ry][lx] = m;
    __syncthreads();
    if (ry == 0) {
        float mm = red[0][lx];
        #pragma unroll
        for (int r = 1; r < 8; r++) mm = fmaxf(mm, red[r][lx]);
        s_mx[lx] = mm;
    }
    __syncthreads();
    const float mx = s_mx[lx];

    float s = 0.f;
    for (int f = ry; f < FDIM; f += 8) {
        float e = __expf(st[f * 33 + lx] - mx);
        st[f * 33 + lx] = e;
        s += e;
    }
    red[ry][lx] = s;
    __syncthreads();
    if (ry == 0) {
        float t = 0.f;
        #pragma unroll
        for (int r = 0; r < 8; r++) t += red[r][lx];
        s_inv[lx] = 1.0f / t;
    }
    __syncthreads();

    const int c       = tid >> 5;
    const int n_local = tid & 31;
    const int n       = c0 + n_local;
    const float inv   = s_inv[n_local];
    const int rot4    = 4 * (n_local & 3);

    #pragma unroll
    for (int sstep = 0; sstep < 4; sstep++) {
        const int kb = c * 64 + sstep * 16;
        float h[16];
        #pragma unroll
        for (int p = 0; p < 16; p++)
            h[p] = st[(kb + p) * 33 + n_local] * inv;
        const int fb = (sstep * 4 + rot4) & 15;
        pack16(g_Wh + (size_t)n * FDIM + c * 64 + fb * 4, h);
    }
}

// ---------------------------------------------------------------------------
// Main: fp16 m16n8k16 GEMM 128x160x512 per CTA, 8 warps (2x4), warp 64x40,
// 2-stage cp.async, 2 CTAs/SM, two-pass register-staged tree epilogue.
// ---------------------------------------------------------------------------
__global__ __launch_bounds__(NTHR, 2)
void detree_mma_kernel(const float* __restrict__ thr,
                       const float* __restrict__ logt,
                       const float* __restrict__ resp,
                       float* __restrict__ out) {
    extern __shared__ char sm[];
    float* s_thr = (float*)(sm + OFF_THR);
    float* s_it  = (float*)(sm + OFF_IT);
    float* s_D   = (float*)sm;                 // [64][162], reuses stage area
    const uint32_t smb = smem_u32(sm);

    const int tid  = threadIdx.x;
    const int lane = tid & 31;
    const int wid  = tid >> 5;
    const int g    = lane >> 2;
    const int tig  = lane & 3;
    const int wm   = wid >> 2;        // 0..1 -> rows wm*64
    const int wn   = wid & 3;         // 0..3 -> cols wn*40
    const int m0    = blockIdx.y * BM;
    const int tree0 = blockIdx.x * TB;
    const int n0    = tree0 * TDEPTH;

    if (tid < TB * TDEPTH) {
        s_thr[tid] = thr[n0 + tid];
        s_it[tid]  = __expf(-logt[n0 + tid]);
    }

    int fb8[4];
    #pragma unroll
    for (int s = 0; s < 4; s++)
        fb8[s] = (((s * 4 + tig) + 4 * (g & 3)) & 15) * 8;
    const int aRow0 = (wm * 64 + g) * 128;             // + mt*2048 (+1024 hi)
    const int bRow0 = 16384 + (wn * 40 + g) * 128;     // + nt*1024

    const __half* aSrcBase = g_Xh + (size_t)m0 * FDIM;
    const __half* bSrcBase = g_Wh + (size_t)n0 * FDIM;

    auto issue_chunk = [&](int i) {
        const uint32_t aB = smb + (i & 1) * STAGE_BYTES;
        const uint32_t bB = aB + 16384;
        const __half* aS = aSrcBase + i * KC;
        const __half* bS = bSrcBase + i * KC;
        #pragma unroll
        for (int r = 0; r < 4; r++) {          // A: 1024 quads
            int id = tid + r * NTHR;
            int row = id >> 3, q = id & 7;
            cpa16(aB + row * 128 + q * 16, aS + (size_t)row * FDIM + q * 8);
        }
        #pragma unroll
        for (int r = 0; r < 5; r++) {          // B: 1280 quads
            int id = tid + r * NTHR;
            int row = id >> 3, q = id & 7;
            cpa16(bB + row * 128 + q * 16, bS + (size_t)row * FDIM + q * 8);
        }
        CP_COMMIT();
    };

    float d[4][5][4];
    #pragma unroll
    for (int mt = 0; mt < 4; mt++)
        #pragma unroll
        for (int nt = 0; nt < 5; nt++)
            #pragma unroll
            for (int q = 0; q < 4; q++) d[mt][nt][q] = 0.f;

    issue_chunk(0);

    for (int i = 0; i < NCHUNK; i++) {
        if (i + 1 < NCHUNK) {                  // stage (i+1)&1 freed by the
            issue_chunk(i + 1);                // trailing barrier of iter i-1
            asm volatile("cp.async.wait_group 1;" ::: "memory");
        } else {
            asm volatile("cp.async.wait_group 0;" ::: "memory");
        }
        __syncthreads();                       // chunk i visible

        const char* stB = sm + (i & 1) * STAGE_BYTES;
        #pragma unroll
        for (int s = 0; s < 4; s++) {
            const char* aB = stB + aRow0 + fb8[s];
            const char* bB = stB + bRow0 + fb8[s];
            uint2 aP[4], aQ[4], bf[5];
            #pragma unroll
            for (int mt = 0; mt < 4; mt++) {
                aP[mt] = *(const uint2*)(aB + mt * 2048);
                aQ[mt] = *(const uint2*)(aB + mt * 2048 + 1024);
            }
            #pragma unroll
            for (int nt = 0; nt < 5; nt++)
                bf[nt] = *(const uint2*)(bB + nt * 1024);
            #pragma unroll
            for (int mt = 0; mt < 4; mt++)
                #pragma unroll
                for (int nt = 0; nt < 5; nt++)
                    mma16(d[mt][nt], aP[mt], aQ[mt], bf[nt]);
        }
        __syncthreads();                       // stage i&1 free for i+2
    }

    // ---- epilogue: two register-staged passes through s_D [64][162] ----
    // Pass p: fragments mt in {2p, 2p+1}; srow = wm*32 + (mt-2p)*16 + g;
    // global row = wm*64 + p*32 + (srow & 31).
    const int tr = tid & 31;
    const int rb = tid >> 5;                   // 0..7
    float ga[5], gb[5];
    #pragma unroll
    for (int dd = 0; dd < TDEPTH; dd++) {
        float it = s_it[tr * 5 + dd];
        ga[dd] = 0.5f * it;
        gb[dd] = 0.5f - s_thr[tr * 5 + dd] * ga[dd];
    }
    float r[16], dr[16];

    #pragma unroll
    for (int p = 0; p < 2; p++) {
        #pragma unroll
        for (int u = 0; u < 2; u++) {
            const int mt = 2 * p + u;
            const int srow = wm * 32 + u * 16 + g;
            #pragma unroll
            for (int nt = 0; nt < 5; nt++) {
                const int col = wn * 40 + nt * 8 + 2 * tig;
                *(float2*)&s_D[srow * 162 + col] =
                    make_float2(d[mt][nt][0], d[mt][nt][1]);
                *(float2*)&s_D[(srow + 8) * 162 + col] =
                    make_float2(d[mt][nt][2], d[mt][nt][3]);
            }
        }
        if (p == 0) {                          // d[0..1] dead: load response
            #pragma unroll
            for (int q = 0; q < 4; q++) {
                float4 vl = *(const float4*)
                    &resp[(size_t)(tree0 + tr) * NLEAF + q * 4];
                float4 vh = *(const float4*)
                    &resp[(size_t)(tree0 + tr) * NLEAF + 16 + q * 4];
                r[4 * q + 0] = vl.x; r[4 * q + 1] = vl.y;
                r[4 * q + 2] = vl.z; r[4 * q + 3] = vl.w;
                dr[4 * q + 0] = vh.x - vl.x; dr[4 * q + 1] = vh.y - vl.y;
                dr[4 * q + 2] = vh.z - vl.z; dr[4 * q + 3] = vh.w - vl.w;
            }
        }
        __syncthreads();

        #pragma unroll
        for (int t = 0; t < 8; t++) {
            const int srow = rb + t * 8;
            const int grow = (srow >> 5) * 64 + p * 32 + (srow & 31);
            const float* fv = &s_D[srow * 162 + tr * 5];
            float c1a[5];
            #pragma unroll
            for (int dd = 0; dd < TDEPTH; dd++)
                c1a[dd] = fma_sat(fv[dd], ga[dd], gb[dd]);

            float s4[16];
            #pragma unroll
            for (int i2 = 0; i2 < 16; i2++)
                s4[i2] = fmaf(c1a[4], dr[i2], r[i2]);
            float s3[8];
            #pragma unroll
            for (int i2 = 0; i2 < 8; i2++)
                s3[i2] = fmaf(c1a[3], s4[i2 + 8] - s4[i2], s4[i2]);
            float s2[4];
            #pragma unroll
            for (int i2 = 0; i2 < 4; i2++)
                s2[i2] = fmaf(c1a[2], s3[i2 + 4] - s3[i2], s3[i2]);
            float s1[2];
            #pragma unroll
            for (int i2 = 0; i2 < 2; i2++)
                s1[i2] = fmaf(c1a[1], s2[i2 + 2] - s2[i2], s2[i2]);
            float ssum = fmaf(c1a[0], s1[1] - s1[0], s1[0]);

            out[(size_t)(m0 + grow) * NTREES + tree0 + tr] = ssum;
        }
        if (p == 0) __syncthreads();           // s_D free for pass 1
    }
}

extern "C" void kernel_launch(void* const* d_in, const int* in_sizes, int n_in,
                              void* d_out, int out_size) {
    const float* x    = (const float*)d_in[0];
    const float* fa   = (const float*)d_in[1];
    const float* thr  = (const float*)d_in[2];
    const float* logt = (const float*)d_in[3];
    const float* resp = (const float*)d_in[4];
    float* out = (float*)d_out;

    const int sm_prep = 512 * 33 * 4;
    cudaFuncSetAttribute(prep_kernel,
                         cudaFuncAttributeMaxDynamicSharedMemorySize, sm_prep);
    cudaFuncSetAttribute(detree_mma_kernel,
                         cudaFuncAttributeMaxDynamicSharedMemorySize, SMEM_BYTES);

    prep_kernel<<<80 + 128, 256, sm_prep>>>(fa, x);
    detree_mma_kernel<<<dim3(NTREES / TB, BATCH / BM), NTHR, SMEM_BYTES>>>(
        thr, logt, resp, out);
}